// round 1
// baseline (speedup 1.0000x reference)
#include <cuda_runtime.h>

// Problem constants
#define BATCH 2
#define SEQ   2048
#define DMODEL 768
#define NHEAD 12
#define HDIM  64
#define MROWS (BATCH*SEQ)   // 4096

// Scratch for Q/K/V in [B, H, S, hd] layout (12 MB each) — device globals, no allocs.
__device__ float g_q[BATCH*NHEAD*SEQ*HDIM];
__device__ float g_k[BATCH*NHEAD*SEQ*HDIM];
__device__ float g_v[BATCH*NHEAD*SEQ*HDIM];

// ---------------------------------------------------------------------------
// Kernel 1: fused QKV projection.  out = X @ W + b, written to [B,H,S,hd].
// Tiled SGEMM: 64x64 tile, BK=16, 256 threads, 4x4 microtile per thread.
// blockIdx.z in {0,1,2} selects Q/K/V.
// ---------------------------------------------------------------------------
__global__ __launch_bounds__(256) void qkv_kernel(
    const float* __restrict__ X,
    const float* __restrict__ Wq, const float* __restrict__ bq,
    const float* __restrict__ Wk, const float* __restrict__ bk,
    const float* __restrict__ Wv, const float* __restrict__ bv)
{
    const int z = blockIdx.z;
    const float* __restrict__ W    = (z == 0) ? Wq : (z == 1) ? Wk : Wv;
    const float* __restrict__ bias = (z == 0) ? bq : (z == 1) ? bk : bv;
    float* __restrict__ out        = (z == 0) ? g_q : (z == 1) ? g_k : g_v;

    __shared__ float As[16][65];   // [k][m], padded
    __shared__ float Bs[16][64];   // [k][n]

    const int tid = threadIdx.x;
    const int tx = tid & 15;
    const int ty = tid >> 4;
    const int m0 = blockIdx.y * 64;
    const int n0 = blockIdx.x * 64;

    float acc[4][4] = {};

    for (int k0 = 0; k0 < DMODEL; k0 += 16) {
        // Load A tile: 64 rows x 16 cols  (1024 elems / 256 threads)
        #pragma unroll
        for (int e = 0; e < 4; e++) {
            int idx = tid + e * 256;
            int r = idx >> 4, c = idx & 15;
            As[c][r] = X[(m0 + r) * DMODEL + k0 + c];
        }
        // Load B tile: 16 rows x 64 cols
        #pragma unroll
        for (int e = 0; e < 4; e++) {
            int idx = tid + e * 256;
            int r = idx >> 6, c = idx & 63;
            Bs[r][c] = W[(k0 + r) * DMODEL + n0 + c];
        }
        __syncthreads();

        #pragma unroll
        for (int k = 0; k < 16; k++) {
            float a[4], b[4];
            #pragma unroll
            for (int i = 0; i < 4; i++) a[i] = As[k][ty + 16 * i];
            #pragma unroll
            for (int j = 0; j < 4; j++) b[j] = Bs[k][tx + 16 * j];
            #pragma unroll
            for (int i = 0; i < 4; i++)
                #pragma unroll
                for (int j = 0; j < 4; j++)
                    acc[i][j] += a[i] * b[j];
        }
        __syncthreads();
    }

    // Epilogue: add bias, scatter into [B,H,S,hd]
    #pragma unroll
    for (int i = 0; i < 4; i++) {
        int mg = m0 + ty + 16 * i;          // global row in [0,4096)
        int bb = mg >> 11;                  // / SEQ
        int s  = mg & (SEQ - 1);
        #pragma unroll
        for (int j = 0; j < 4; j++) {
            int ng = n0 + tx + 16 * j;      // global col in [0,768)
            int h  = ng >> 6;
            int d  = ng & 63;
            out[((bb * NHEAD + h) * SEQ + s) * HDIM + d] = acc[i][j] + bias[ng];
        }
    }
}

// ---------------------------------------------------------------------------
// Kernel 2: flash attention.  One block per (b,h, q-tile of 64 rows).
// BM=BN=64, online softmax, O[64][64] in registers (4x4 per thread).
// smem: Qs/Ks/Vs each [64][65] fp32 (padded, conflict-free).  Ks reused as Ps.
// ---------------------------------------------------------------------------
__global__ __launch_bounds__(256) void attn_kernel(
    const float* __restrict__ mask, float* __restrict__ out)
{
    extern __shared__ float smem[];
    float* Qs = smem;              // [64][65]
    float* Ks = smem + 64 * 65;    // [64][65], reused as P
    float* Vs = Ks  + 64 * 65;     // [64][65]

    const int pair = blockIdx.y;
    const int bb = pair / NHEAD;
    const int h  = pair % NHEAD;
    const int q0 = blockIdx.x * 64;

    const int tid = threadIdx.x;
    const int tx = tid & 15;
    const int ty = tid >> 4;

    const float* __restrict__ Qg = g_q + (bb * NHEAD + h) * SEQ * HDIM;
    const float* __restrict__ Kg = g_k + (bb * NHEAD + h) * SEQ * HDIM;
    const float* __restrict__ Vg = g_v + (bb * NHEAD + h) * SEQ * HDIM;

    // Load Q tile once (4096 elems / 256 threads = 16 each)
    #pragma unroll
    for (int e = 0; e < 16; e++) {
        int idx = tid + e * 256;
        int r = idx >> 6, d = idx & 63;
        Qs[r * 65 + d] = Qg[(q0 + r) * HDIM + d];
    }

    float m_r[4], l_r[4], o[4][4] = {};
    #pragma unroll
    for (int i = 0; i < 4; i++) { m_r[i] = -1e30f; l_r[i] = 0.f; }

    for (int k0 = 0; k0 < SEQ; k0 += 64) {
        __syncthreads();  // previous-iter reads of Ks/Vs done; also covers Q load on iter 0
        #pragma unroll
        for (int e = 0; e < 16; e++) {
            int idx = tid + e * 256;
            int r = idx >> 6, d = idx & 63;
            Ks[r * 65 + d] = Kg[(k0 + r) * HDIM + d];
            Vs[r * 65 + d] = Vg[(k0 + r) * HDIM + d];
        }
        __syncthreads();

        // S = Q K^T  (64x64 tile, 4x4 per thread)
        float s[4][4] = {};
        #pragma unroll
        for (int d = 0; d < 64; d++) {
            float a[4], b[4];
            #pragma unroll
            for (int i = 0; i < 4; i++) a[i] = Qs[(ty + 16 * i) * 65 + d];
            #pragma unroll
            for (int j = 0; j < 4; j++) b[j] = Ks[(tx + 16 * j) * 65 + d];
            #pragma unroll
            for (int i = 0; i < 4; i++)
                #pragma unroll
                for (int j = 0; j < 4; j++)
                    s[i][j] += a[i] * b[j];
        }

        // scale + additive mask (mask indexed by key position)
        float mk[4];
        #pragma unroll
        for (int j = 0; j < 4; j++)
            mk[j] = mask[bb * SEQ + k0 + tx + 16 * j];

        // online softmax update.  Row r = ty+16*i is owned by the 16 lanes
        // sharing ty (contiguous half-warp) -> shfl width-16 reductions.
        #pragma unroll
        for (int i = 0; i < 4; i++) {
            float mm = -1e30f;
            #pragma unroll
            for (int j = 0; j < 4; j++) {
                s[i][j] = s[i][j] * 0.125f + mk[j];   // 1/sqrt(64)
                mm = fmaxf(mm, s[i][j]);
            }
            #pragma unroll
            for (int off = 8; off > 0; off >>= 1)
                mm = fmaxf(mm, __shfl_xor_sync(0xffffffffu, mm, off, 16));

            float mn = fmaxf(m_r[i], mm);
            float alpha = __expf(m_r[i] - mn);
            m_r[i] = mn;

            float ps = 0.f;
            #pragma unroll
            for (int j = 0; j < 4; j++) {
                s[i][j] = __expf(s[i][j] - mn);
                ps += s[i][j];
            }
            #pragma unroll
            for (int off = 8; off > 0; off >>= 1)
                ps += __shfl_xor_sync(0xffffffffu, ps, off, 16);

            l_r[i] = l_r[i] * alpha + ps;
            #pragma unroll
            for (int j = 0; j < 4; j++) o[i][j] *= alpha;
        }

        __syncthreads();   // all threads done reading Ks as K
        // stage P into Ks region
        #pragma unroll
        for (int i = 0; i < 4; i++)
            #pragma unroll
            for (int j = 0; j < 4; j++)
                Ks[(ty + 16 * i) * 65 + tx + 16 * j] = s[i][j];
        __syncthreads();

        // O += P @ V
        #pragma unroll
        for (int c = 0; c < 64; c++) {
            float a[4], b[4];
            #pragma unroll
            for (int i = 0; i < 4; i++) a[i] = Ks[(ty + 16 * i) * 65 + c];
            #pragma unroll
            for (int j = 0; j < 4; j++) b[j] = Vs[c * 65 + tx + 16 * j];
            #pragma unroll
            for (int i = 0; i < 4; i++)
                #pragma unroll
                for (int j = 0; j < 4; j++)
                    o[i][j] += a[i] * b[j];
        }
    }

    // Normalize and write out in [B,S,D]
    #pragma unroll
    for (int i = 0; i < 4; i++) {
        int r = q0 + ty + 16 * i;
        float inv = 1.f / l_r[i];
        #pragma unroll
        for (int j = 0; j < 4; j++) {
            int d = tx + 16 * j;
            out[(bb * SEQ + r) * DMODEL + h * HDIM + d] = o[i][j] * inv;
        }
    }
}

// ---------------------------------------------------------------------------
extern "C" void kernel_launch(void* const* d_in, const int* in_sizes, int n_in,
                              void* d_out, int out_size)
{
    const float* v1   = (const float*)d_in[0];
    const float* mask = (const float*)d_in[1];
    const float* Wq   = (const float*)d_in[2];
    const float* bq   = (const float*)d_in[3];
    const float* Wk   = (const float*)d_in[4];
    const float* bk   = (const float*)d_in[5];
    const float* Wv   = (const float*)d_in[6];
    const float* bv   = (const float*)d_in[7];
    float* out = (float*)d_out;

    // QKV projections: grid (N-tiles, M-tiles, 3)
    dim3 g1(DMODEL / 64, MROWS / 64, 3);
    qkv_kernel<<<g1, 256>>>(v1, Wq, bq, Wk, bk, Wv, bv);

    // Attention: grid (q-tiles, B*H).  49920 B dynamic smem (> 48 KB static cap).
    const int smem_bytes = 3 * 64 * 65 * (int)sizeof(float);
    cudaFuncSetAttribute(attn_kernel, cudaFuncAttributeMaxDynamicSharedMemorySize,
                         smem_bytes);
    dim3 g2(SEQ / 64, BATCH * NHEAD);
    attn_kernel<<<g2, 256, smem_bytes>>>(mask, out);
}